// round 7
// baseline (speedup 1.0000x reference)
#include <cuda_runtime.h>
#include <cstdint>

#define MDIM 4096
#define NDIM 4096
#define KDIM 4096
#define BM 128
#define BN 128
#define BK 32
#define PAD 4
#define LDS (BK + PAD)          // 36 floats per smem row
#define NTHREADS 256
#define NKTILES (KDIM / BK)     // 128
#define BUF_FLOATS (BM * LDS)
#define SMEM_BYTES (4 * BUF_FLOATS * 4)  // 73728 B (A+B double-buffered)

// tf32-rounded, k-permuted copies of X and W (static device scratch is allowed)
__device__ __align__(1024) float g_Xtf[(size_t)MDIM * KDIM];
__device__ __align__(1024) float g_Wtf[(size_t)NDIM * KDIM];

__device__ __forceinline__ float f_rna(float x) {
    uint32_t r;
    asm volatile("cvt.rna.tf32.f32 %0, %1;" : "=r"(r) : "f"(x));
    return __uint_as_float(r);
}

__device__ __forceinline__ void cp_async16(uint32_t saddr, const float* g) {
    asm volatile("cp.async.cg.shared.global [%0], [%1], 16;" :: "r"(saddr), "l"(g));
}

// ---- pre-pass: RNA-round to tf32 AND permute each 8-float k-group to
//      [0,4,1,5,2,6,3,7] so mma fragment (col, col+4) pairs are adjacent.
__global__ void __launch_bounds__(256)
cvt_perm_kernel(const float4* __restrict__ in, float4* __restrict__ out, int ngroups) {
    int i = blockIdx.x * blockDim.x + threadIdx.x;
    const int stride = gridDim.x * blockDim.x;
    for (; i < ngroups; i += stride) {
        float4 x0 = in[2 * i];       // j0..j3
        float4 x1 = in[2 * i + 1];   // j4..j7
        float4 o0, o1;
        o0.x = f_rna(x0.x); o0.y = f_rna(x1.x);   // j0, j4
        o0.z = f_rna(x0.y); o0.w = f_rna(x1.y);   // j1, j5
        o1.x = f_rna(x0.z); o1.y = f_rna(x1.z);   // j2, j6
        o1.z = f_rna(x0.w); o1.w = f_rna(x1.w);   // j3, j7
        out[2 * i]     = o0;
        out[2 * i + 1] = o1;
    }
}

__global__ __launch_bounds__(NTHREADS, 2)
void gemm_tf32_kernel(const float* __restrict__ X, const float* __restrict__ W,
                      const float* __restrict__ bias, float* __restrict__ Out) {
    extern __shared__ float smem[];
    float* As = smem;                       // [2][BM][LDS]
    float* Bs = smem + 2 * BUF_FLOATS;      // [2][BN][LDS]

    const int tid  = threadIdx.x;
    const int warp = tid >> 5;
    const int lane = tid & 31;
    const int bm   = blockIdx.y;
    const int bn   = blockIdx.x;

    const int warp_m = (warp >> 2) * 64;    // 0 or 64
    const int warp_n = (warp & 3) * 32;     // 0,32,64,96

    // ---- global -> shared: 4 float4 per thread per tile for A and B
    const int grow = tid >> 3;              // 0..31 (+=32 per i)
    const int gcol = (tid & 7) * 4;
    const float* xg = X + (size_t)(bm * BM + grow) * KDIM + gcol;
    const float* wg = W + (size_t)(bn * BN + grow) * KDIM + gcol;

    uint32_t as_addr = (uint32_t)__cvta_generic_to_shared(As + grow * LDS + gcol);
    uint32_t bs_addr = (uint32_t)__cvta_generic_to_shared(Bs + grow * LDS + gcol);
    const uint32_t buf_bytes = BUF_FLOATS * 4;

    float acc[4][4][4];
#pragma unroll
    for (int mi = 0; mi < 4; mi++)
#pragma unroll
        for (int ni = 0; ni < 4; ni++)
#pragma unroll
            for (int r = 0; r < 4; r++) acc[mi][ni][r] = 0.0f;

    const int qrow = lane >> 2;   // 0..7
    const int qcol = lane & 3;    // 0..3

    // prologue: tile 0 -> buffer 0
    {
#pragma unroll
        for (int i = 0; i < 4; i++) {
            cp_async16(as_addr + i * (32 * LDS * 4), xg + (size_t)i * 32 * KDIM);
            cp_async16(bs_addr + i * (32 * LDS * 4), wg + (size_t)i * 32 * KDIM);
        }
        asm volatile("cp.async.commit_group;");
    }

#pragma unroll 1
    for (int kb = 0; kb < NKTILES; kb++) {
        const int buf = kb & 1;

        if (kb + 1 < NKTILES) {
            const float* xp = xg + (size_t)(kb + 1) * BK;
            const float* wp = wg + (size_t)(kb + 1) * BK;
            const uint32_t off = (buf ^ 1) * buf_bytes;
#pragma unroll
            for (int i = 0; i < 4; i++) {
                cp_async16(as_addr + off + i * (32 * LDS * 4), xp + (size_t)i * 32 * KDIM);
                cp_async16(bs_addr + off + i * (32 * LDS * 4), wp + (size_t)i * 32 * KDIM);
            }
            asm volatile("cp.async.commit_group;");
            asm volatile("cp.async.wait_group 1;");
        } else {
            asm volatile("cp.async.wait_group 0;");
        }
        __syncthreads();

        const float* A0 = As + buf * BUF_FLOATS + warp_m * LDS;
        const float* B0 = Bs + buf * BUF_FLOATS + warp_n * LDS;

#pragma unroll
        for (int kk = 0; kk < 4; kk++) {
            // permuted layout: cols (qcol, qcol+4) of this k-group sit at
            // float positions (2*qcol, 2*qcol+1) -> one LDS.64 each.
            uint2 alo[4], ahi[4];
#pragma unroll
            for (int mi = 0; mi < 4; mi++) {
                const float* ap = A0 + (mi * 16 + qrow) * LDS + kk * 8;
                alo[mi] = reinterpret_cast<const uint2*>(ap)[qcol];            // a0,a2
                ahi[mi] = reinterpret_cast<const uint2*>(ap + 8 * LDS)[qcol];  // a1,a3
            }
            uint2 b[4];
#pragma unroll
            for (int ni = 0; ni < 4; ni++) {
                const float* bp = B0 + (ni * 8 + qrow) * LDS + kk * 8;
                b[ni] = reinterpret_cast<const uint2*>(bp)[qcol];              // b0,b1
            }

#pragma unroll
            for (int mi = 0; mi < 4; mi++) {
#pragma unroll
                for (int ni = 0; ni < 4; ni++) {
                    asm volatile(
                        "mma.sync.aligned.m16n8k8.row.col.f32.tf32.tf32.f32 "
                        "{%0,%1,%2,%3}, {%4,%5,%6,%7}, {%8,%9}, {%0,%1,%2,%3};"
                        : "+f"(acc[mi][ni][0]), "+f"(acc[mi][ni][1]),
                          "+f"(acc[mi][ni][2]), "+f"(acc[mi][ni][3])
                        : "r"(alo[mi].x), "r"(ahi[mi].x), "r"(alo[mi].y), "r"(ahi[mi].y),
                          "r"(b[ni].x), "r"(b[ni].y));
                }
            }
        }
        __syncthreads();
    }

    // ---- epilogue: bias add + store
    const int row0 = bm * BM + warp_m + qrow;
    const int col0 = bn * BN + warp_n + 2 * qcol;

    float2 bv[4];
#pragma unroll
    for (int ni = 0; ni < 4; ni++) {
        bv[ni].x = bias[col0 + ni * 8];
        bv[ni].y = bias[col0 + ni * 8 + 1];
    }

#pragma unroll
    for (int mi = 0; mi < 4; mi++) {
        const int r = row0 + mi * 16;
#pragma unroll
        for (int ni = 0; ni < 4; ni++) {
            const int c = col0 + ni * 8;
            float2 v0 = make_float2(acc[mi][ni][0] + bv[ni].x, acc[mi][ni][1] + bv[ni].y);
            float2 v1 = make_float2(acc[mi][ni][2] + bv[ni].x, acc[mi][ni][3] + bv[ni].y);
            *reinterpret_cast<float2*>(&Out[(size_t)r * NDIM + c]) = v0;
            *reinterpret_cast<float2*>(&Out[(size_t)(r + 8) * NDIM + c]) = v1;
        }
    }
}

extern "C" void kernel_launch(void* const* d_in, const int* in_sizes, int n_in,
                              void* d_out, int out_size) {
    const float* x    = (const float*)d_in[0];
    const float* w    = (const float*)d_in[1];
    const float* bias = (const float*)d_in[2];
    float* out        = (float*)d_out;

    void* pX = nullptr; void* pW = nullptr;
    cudaGetSymbolAddress(&pX, g_Xtf);
    cudaGetSymbolAddress(&pW, g_Wtf);

    const int ngroups = (MDIM * KDIM) / 8;   // 8-float k-groups per matrix
    cvt_perm_kernel<<<2048, 256>>>((const float4*)x, (float4*)pX, ngroups);
    cvt_perm_kernel<<<2048, 256>>>((const float4*)w, (float4*)pW, ngroups);

    cudaFuncSetAttribute(gemm_tf32_kernel,
                         cudaFuncAttributeMaxDynamicSharedMemorySize, SMEM_BYTES);

    dim3 grid(NDIM / BN, MDIM / BM);   // 32 x 32 = 1024 CTAs
    gemm_tf32_kernel<<<grid, NTHREADS, SMEM_BYTES>>>((const float*)pX, (const float*)pW,
                                                     bias, out);
}

// round 8
// speedup vs baseline: 1.1682x; 1.1682x over previous
#include <cuda_runtime.h>
#include <cstdint>

#define MDIM 4096
#define NDIM 4096
#define KDIM 4096
#define BM 128
#define BN 128
#define BK 16
#define ROWF 24                          // smem row stride in floats (conflict-free LDS.64)
#define NKT (KDIM / BK)                  // 256
#define ST 4                             // pipeline stages
#define NTHREADS 128                     // 4 warps, 64x64 warp tiles
#define STAGE_FLOATS (BM * ROWF)         // 3072 floats = 12KB per matrix per stage
#define SMEM_BYTES (2 * ST * STAGE_FLOATS * 4)   // 98304 B

// tf32-rounded, k-permuted copies of X and W (static device scratch)
__device__ __align__(1024) float g_Xtf[(size_t)MDIM * KDIM];
__device__ __align__(1024) float g_Wtf[(size_t)NDIM * KDIM];

__device__ __forceinline__ float f_rna(float x) {
    uint32_t r;
    asm volatile("cvt.rna.tf32.f32 %0, %1;" : "=r"(r) : "f"(x));
    return __uint_as_float(r);
}

__device__ __forceinline__ void cp_async16(uint32_t saddr, const float* g) {
    asm volatile("cp.async.cg.shared.global [%0], [%1], 16;" :: "r"(saddr), "l"(g));
}

// ---- pre-pass: RNA-round to tf32 AND permute each 8-float k-group to
//      [0,4,1,5,2,6,3,7] so each mma fragment (col, col+4) pair is one LDS.64.
__global__ void __launch_bounds__(256)
cvt_perm_kernel(const float4* __restrict__ in, float4* __restrict__ out, int ngroups) {
    int i = blockIdx.x * blockDim.x + threadIdx.x;
    const int stride = gridDim.x * blockDim.x;
    for (; i < ngroups; i += stride) {
        float4 x0 = in[2 * i];
        float4 x1 = in[2 * i + 1];
        float4 o0, o1;
        o0.x = f_rna(x0.x); o0.y = f_rna(x1.x);
        o0.z = f_rna(x0.y); o0.w = f_rna(x1.y);
        o1.x = f_rna(x0.z); o1.y = f_rna(x1.z);
        o1.z = f_rna(x0.w); o1.w = f_rna(x1.w);
        out[2 * i]     = o0;
        out[2 * i + 1] = o1;
    }
}

#define MMA_TF32(ACC, ALO, AHI, B)                                              \
    asm volatile(                                                                \
        "mma.sync.aligned.m16n8k8.row.col.f32.tf32.tf32.f32 "                    \
        "{%0,%1,%2,%3}, {%4,%5,%6,%7}, {%8,%9}, {%0,%1,%2,%3};"                  \
        : "+f"((ACC)[0]), "+f"((ACC)[1]), "+f"((ACC)[2]), "+f"((ACC)[3])         \
        : "r"((ALO).x), "r"((AHI).x), "r"((ALO).y), "r"((AHI).y),                \
          "r"((B).x), "r"((B).y))

__global__ __launch_bounds__(NTHREADS, 2)
void gemm_tf32_kernel(const float* __restrict__ X, const float* __restrict__ W,
                      const float* __restrict__ bias, float* __restrict__ Out) {
    extern __shared__ float smem[];
    float* As = smem;                         // [ST][BM][ROWF]
    float* Bs = smem + ST * STAGE_FLOATS;     // [ST][BN][ROWF]

    const int tid  = threadIdx.x;
    const int warp = tid >> 5;
    const int lane = tid & 31;
    const int bm   = blockIdx.y;
    const int bn   = blockIdx.x;

    const int warp_m = (warp >> 1) * 64;      // 0 or 64
    const int warp_n = (warp & 1) * 64;       // 0 or 64

    const int qrow = lane >> 2;               // 0..7
    const int qcol = lane & 3;                // 0..3

    // global->shared: 128 rows x 4 chunks(16B) = 512 tasks; 4 per thread
    const int grow   = tid >> 2;              // 0..31 (+32 per i)
    const int gchunk = (tid & 3) * 4;         // float offset in row
    const float* xg = X + (size_t)(bm * BM + grow) * KDIM + gchunk;
    const float* wg = W + (size_t)(bn * BN + grow) * KDIM + gchunk;
    uint32_t as0 = (uint32_t)__cvta_generic_to_shared(As + grow * ROWF + gchunk);
    uint32_t bs0 = (uint32_t)__cvta_generic_to_shared(Bs + grow * ROWF + gchunk);
    const uint32_t stage_bytes = STAGE_FLOATS * 4;

    float acc[4][8][4];
#pragma unroll
    for (int mi = 0; mi < 4; mi++)
#pragma unroll
        for (int ni = 0; ni < 8; ni++)
#pragma unroll
            for (int r = 0; r < 4; r++) acc[mi][ni][r] = 0.0f;

    // ---- prologue: stages 0..ST-2
#pragma unroll
    for (int s = 0; s < ST - 1; s++) {
        const float* xp = xg + (size_t)s * BK;
        const float* wp = wg + (size_t)s * BK;
        const uint32_t off = s * stage_bytes;
#pragma unroll
        for (int i = 0; i < 4; i++) {
            cp_async16(as0 + off + i * (32 * ROWF * 4), xp + (size_t)i * 32 * KDIM);
            cp_async16(bs0 + off + i * (32 * ROWF * 4), wp + (size_t)i * 32 * KDIM);
        }
        asm volatile("cp.async.commit_group;");
    }

#pragma unroll 1
    for (int kb = 0; kb < NKT; kb++) {
        const int snext = kb + ST - 1;
        if (snext < NKT) {
            asm volatile("cp.async.wait_group 2;");
        } else {
            asm volatile("cp.async.wait_group 0;");
        }
        __syncthreads();

        if (snext < NKT) {
            const float* xp = xg + (size_t)snext * BK;
            const float* wp = wg + (size_t)snext * BK;
            const uint32_t off = (snext & (ST - 1)) * stage_bytes;
#pragma unroll
            for (int i = 0; i < 4; i++) {
                cp_async16(as0 + off + i * (32 * ROWF * 4), xp + (size_t)i * 32 * KDIM);
                cp_async16(bs0 + off + i * (32 * ROWF * 4), wp + (size_t)i * 32 * KDIM);
            }
            asm volatile("cp.async.commit_group;");
        }

        const int s = kb & (ST - 1);
        const float* A0 = As + s * STAGE_FLOATS + warp_m * ROWF;
        const float* B0 = Bs + s * STAGE_FLOATS + warp_n * ROWF;

        uint2 alo[2][4], ahi[2][4], bb[2][8];
        // load k-step 0 fragments
#pragma unroll
        for (int mi = 0; mi < 4; mi++) {
            const float* ap = A0 + (mi * 16 + qrow) * ROWF;
            alo[0][mi] = reinterpret_cast<const uint2*>(ap)[qcol];
            ahi[0][mi] = reinterpret_cast<const uint2*>(ap + 8 * ROWF)[qcol];
        }
#pragma unroll
        for (int ni = 0; ni < 8; ni++) {
            const float* bp = B0 + (ni * 8 + qrow) * ROWF;
            bb[0][ni] = reinterpret_cast<const uint2*>(bp)[qcol];
        }

#pragma unroll
        for (int kk = 0; kk < 2; kk++) {
            if (kk == 0) {   // prefetch k-step 1 while issuing k-step 0 MMAs
#pragma unroll
                for (int mi = 0; mi < 4; mi++) {
                    const float* ap = A0 + (mi * 16 + qrow) * ROWF + 8;
                    alo[1][mi] = reinterpret_cast<const uint2*>(ap)[qcol];
                    ahi[1][mi] = reinterpret_cast<const uint2*>(ap + 8 * ROWF)[qcol];
                }
#pragma unroll
                for (int ni = 0; ni < 8; ni++) {
                    const float* bp = B0 + (ni * 8 + qrow) * ROWF + 8;
                    bb[1][ni] = reinterpret_cast<const uint2*>(bp)[qcol];
                }
            }
#pragma unroll
            for (int mi = 0; mi < 4; mi++)
#pragma unroll
                for (int ni = 0; ni < 8; ni++)
                    MMA_TF32(acc[mi][ni], alo[kk][mi], ahi[kk][mi], bb[kk][ni]);
        }
    }

    // ---- epilogue: bias add + float2 stores
    const int row0 = bm * BM + warp_m + qrow;
    const int col0 = bn * BN + warp_n + 2 * qcol;

    float2 bv[8];
#pragma unroll
    for (int ni = 0; ni < 8; ni++) {
        bv[ni].x = bias[col0 + ni * 8];
        bv[ni].y = bias[col0 + ni * 8 + 1];
    }

#pragma unroll
    for (int mi = 0; mi < 4; mi++) {
        const int r = row0 + mi * 16;
#pragma unroll
        for (int ni = 0; ni < 8; ni++) {
            const int c = col0 + ni * 8;
            float2 v0 = make_float2(acc[mi][ni][0] + bv[ni].x, acc[mi][ni][1] + bv[ni].y);
            float2 v1 = make_float2(acc[mi][ni][2] + bv[ni].x, acc[mi][ni][3] + bv[ni].y);
            *reinterpret_cast<float2*>(&Out[(size_t)r * NDIM + c]) = v0;
            *reinterpret_cast<float2*>(&Out[(size_t)(r + 8) * NDIM + c]) = v1;
        }
    }
}

extern "C" void kernel_launch(void* const* d_in, const int* in_sizes, int n_in,
                              void* d_out, int out_size) {
    const float* x    = (const float*)d_in[0];
    const float* w    = (const float*)d_in[1];
    const float* bias = (const float*)d_in[2];
    float* out        = (float*)d_out;

    void* pX = nullptr; void* pW = nullptr;
    cudaGetSymbolAddress(&pX, g_Xtf);
    cudaGetSymbolAddress(&pW, g_Wtf);

    const int ngroups = (MDIM * KDIM) / 8;
    cvt_perm_kernel<<<4096, 256>>>((const float4*)x, (float4*)pX, ngroups);
    cvt_perm_kernel<<<4096, 256>>>((const float4*)w, (float4*)pW, ngroups);

    cudaFuncSetAttribute(gemm_tf32_kernel,
                         cudaFuncAttributeMaxDynamicSharedMemorySize, SMEM_BYTES);

    dim3 grid(NDIM / BN, MDIM / BM);   // 32 x 32 = 1024 CTAs
    gemm_tf32_kernel<<<grid, NTHREADS, SMEM_BYTES>>>((const float*)pX, (const float*)pW,
                                                     bias, out);
}